// round 8
// baseline (speedup 1.0000x reference)
#include <cuda_runtime.h>

#define BATCH 128
#define SEQ   2048
#define FEAT  64
#define UNITS 64
#define GATES 256   // 4*UNITS
#define OUTD  6

// Precomputed x@W0 + b0, PERMUTED column layout, [B][T][256] (+pad: pipeline prefetch overshoots)
__device__ float g_pre0[(size_t)BATCH * SEQ * GATES + 4 * GATES];

typedef unsigned long long u64;

// ---- packed f32x2 helpers -------------------------------------------------
__device__ __forceinline__ u64 pk(float lo, float hi) {
    u64 r; asm("mov.b64 %0, {%1, %2};" : "=l"(r) : "f"(lo), "f"(hi)); return r;
}
__device__ __forceinline__ void upk(u64 v, float& lo, float& hi) {
    asm("mov.b64 {%0, %1}, %2;" : "=f"(lo), "=f"(hi) : "l"(v));
}
__device__ __forceinline__ void fma2(u64& d, u64 a, u64 b) {
    asm("fma.rn.f32x2 %0, %1, %2, %0;" : "+l"(d) : "l"(a), "l"(b));
}
__device__ __forceinline__ u64 addx2(u64 a, u64 b) {
    u64 r; asm("add.rn.f32x2 %0, %1, %2;" : "=l"(r) : "l"(a), "l"(b)); return r;
}
__device__ __forceinline__ float red4(u64 a, u64 b) {
    float x0, x1, x2, x3; upk(a, x0, x1); upk(b, x2, x3);
    return (x0 + x1) + (x2 + x3);
}

// ---- raw MUFU helpers (same numerics as __expf/__fdividef path) -----------
__device__ __forceinline__ float ex2_ap(float x) {
    float r; asm("ex2.approx.f32 %0, %1;" : "=f"(r) : "f"(x)); return r;
}
__device__ __forceinline__ float rcp_ap(float x) {
    float r; asm("rcp.approx.f32 %0, %1;" : "=f"(r) : "f"(x)); return r;
}
// act(z) = (1 - s*e) * rcp(1+e), e = 2^(min(m2*z, 40)):
//   sigmoid: m2=-log2e,  s=0 ; tanh: m2=-2log2e, s=1
__device__ __forceinline__ float gate_act(float z, float m2, float s) {
    float e = ex2_ap(fminf(m2 * z, 40.f));
    return (1.f - s * e) * rcp_ap(1.f + e);
}
__device__ __forceinline__ float tanh_fast(float x) {
    float e = ex2_ap(fminf(-2.885390082f * x, 40.f));
    return (1.f - e) * rcp_ap(1.f + e);
}

// Column permutation: column q <-> gate column (q&3)*64 + (q>>2)
__device__ __forceinline__ int PERM(int q) { return ((q & 3) << 6) + (q >> 2); }

// ===========================================================================
// Kernel 1: pre0[b][t][j] = (x[b][t] @ W0 + b0)[PERM(j)], 4-timestep unroll
// ===========================================================================
__global__ void __launch_bounds__(256) precompute_kernel(
    const float* __restrict__ x, const float* __restrict__ W0,
    const float* __restrict__ b0)
{
    __shared__ __align__(16) float xs[128 * FEAT];   // 32 KB
    const int b   = blockIdx.x;
    const int t0  = blockIdx.y * 128;
    const int j   = threadIdx.x;
    const int col = PERM(j);

    u64 w[32];
#pragma unroll
    for (int m = 0; m < 32; m++)
        w[m] = pk(W0[(2 * m) * GATES + col], W0[(2 * m + 1) * GATES + col]);
    const float bias = b0[col];

    const float4* xp = (const float4*)(x + ((size_t)b * SEQ + t0) * FEAT);
    float4* xsv = (float4*)xs;
    for (int i = j; i < 128 * FEAT / 4; i += 256) xsv[i] = xp[i];
    __syncthreads();

    float* outp = g_pre0 + ((size_t)b * SEQ + t0) * GATES;
    for (int t = 0; t < 128; t += 4) {
        u64 acc[8];
#pragma unroll
        for (int r = 0; r < 4; r++) { acc[2 * r] = pk(bias, 0.f); acc[2 * r + 1] = 0ull; }
        const float4* hx0 = (const float4*)(xs + (t + 0) * FEAT);
        const float4* hx1 = (const float4*)(xs + (t + 1) * FEAT);
        const float4* hx2 = (const float4*)(xs + (t + 2) * FEAT);
        const float4* hx3 = (const float4*)(xs + (t + 3) * FEAT);
#pragma unroll
        for (int m = 0; m < 16; m++) {
            float4 q0 = hx0[m];
            fma2(acc[0], pk(q0.x, q0.y), w[2 * m]);
            fma2(acc[1], pk(q0.z, q0.w), w[2 * m + 1]);
            float4 q1 = hx1[m];
            fma2(acc[2], pk(q1.x, q1.y), w[2 * m]);
            fma2(acc[3], pk(q1.z, q1.w), w[2 * m + 1]);
            float4 q2 = hx2[m];
            fma2(acc[4], pk(q2.x, q2.y), w[2 * m]);
            fma2(acc[5], pk(q2.z, q2.w), w[2 * m + 1]);
            float4 q3 = hx3[m];
            fma2(acc[6], pk(q3.x, q3.y), w[2 * m]);
            fma2(acc[7], pk(q3.z, q3.w), w[2 * m + 1]);
        }
#pragma unroll
        for (int r = 0; r < 4; r++)
            outp[(size_t)(t + r) * GATES + j] = red4(acc[2 * r], acc[2 * r + 1]);
    }
}

// ===========================================================================
// Kernel 2: persistent recurrence, CELLS PIPELINED ACROSS TIME, with the
// GEMV loops split PER H-ARRAY so accumulator groups complete staggered:
//   Loop A (H0): z0 (u0) + z1ab (w1)   -> tail0 overlaps Loop B issue
//   Loop B (H1): z1cd (u1) + z2ab (w1) -> tail1 overlaps Loop C issue
//   Loop C (H2): z2cd (u1)             -> only tail2 exposed before barrier
// 128 blocks x 256 threads; 1 barrier/tick; warm-up/drain peeled.
// ===========================================================================
__global__ void __launch_bounds__(256) rnn_kernel(
    const float* __restrict__ U0g, const float* __restrict__ W1g,
    const float* __restrict__ U1g, const float* __restrict__ b1g,
    const float* __restrict__ Wf,  const float* __restrict__ bfv,
    const float* __restrict__ Wo,  const float* __restrict__ bo,
    float* __restrict__ out)
{
    __shared__ __align__(16) float h0buf[2][UNITS];
    __shared__ __align__(16) float h1buf[2][UNITS];
    __shared__ __align__(16) float h2buf[2][UNITS];
    __shared__ __align__(16) float fs[64];

    const int j   = threadIdx.x;          // 0..255
    const int b   = blockIdx.x;
    const int col = PERM(j);
    const int u   = j >> 2;
    const bool wr  = ((j & 3) == 0);
    const bool isg = ((j & 3) == 2);
    const float am2 = isg ? -2.885390082f : -1.442695041f;  // -k*log2(e)
    const float as  = isg ?  1.f : 0.f;

    // Weight columns in registers, k-packed (96 u64 = 192 regs).
    u64 u0[32], w1[32], u1[32];
#pragma unroll
    for (int m = 0; m < 32; m++) {
        u0[m] = pk(U0g[(2 * m) * GATES + col], U0g[(2 * m + 1) * GATES + col]);
        w1[m] = pk(W1g[(2 * m) * GATES + col], W1g[(2 * m + 1) * GATES + col]);
        u1[m] = pk(U1g[(2 * m) * GATES + col], U1g[(2 * m + 1) * GATES + col]);
    }
    const float bias1 = b1g[col];

    float c0 = 0.f, c1 = 0.f, c2 = 0.f;   // valid on g==0 lanes
    if (j < UNITS) {
        h0buf[0][j] = 0.f; h0buf[1][j] = 0.f;
        h1buf[0][j] = 0.f; h1buf[1][j] = 0.f;
        h2buf[0][j] = 0.f; h2buf[1][j] = 0.f;
    }
    __syncthreads();

    const float* prep = g_pre0 + (size_t)b * SEQ * GATES + j;
    float pre = *prep;                    // pre for tau=0

#define UPDATE_CELL(ZA, ZB, CV, DST)                                        \
    {                                                                       \
        float z_ = red4(ZA, ZB);                                            \
        float a_  = gate_act(z_, am2, as);                                  \
        float v1_ = __shfl_xor_sync(0xffffffffu, a_, 1);                    \
        float v2_ = __shfl_xor_sync(0xffffffffu, a_, 2);                    \
        float v3_ = __shfl_xor_sync(0xffffffffu, a_, 3);                    \
        CV = v1_ * CV + a_ * v2_;                                           \
        float h_ = v3_ * tanh_fast(CV);                                     \
        if (wr) (DST)[u] = h_;                                              \
    }

#define TICK(TAU, DC0, DC1, DC2)                                            \
    {                                                                       \
        const int rp_ = (TAU) & 1, wp_ = rp_ ^ 1;                           \
        const float4* H0_ = (const float4*)h0buf[rp_];                      \
        const float4* H1_ = (const float4*)h1buf[rp_];                      \
        const float4* H2_ = (const float4*)h2buf[rp_];                      \
        u64 z0a = pk(pre, 0.f),   z0b = 0ull;                               \
        u64 z1a = pk(bias1, 0.f), z1b = 0ull, z1c = 0ull, z1d = 0ull;       \
        u64 z2a = pk(bias1, 0.f), z2b = 0ull, z2c = 0ull, z2d = 0ull;       \
        prep += GATES;                                                      \
        pre = *prep;                                                        \
        /* Loop A: consumes H0 only -> z0 complete, z1ab partial */         \
        _Pragma("unroll")                                                   \
        for (int m = 0; m < 16; m++) {                                      \
            float4 q0 = H0_[m];                                             \
            u64 a0 = pk(q0.x, q0.y), a1 = pk(q0.z, q0.w);                   \
            if (DC0) { fma2(z0a, a0, u0[2*m]); fma2(z0b, a1, u0[2*m+1]); }  \
            if (DC1) { fma2(z1a, a0, w1[2*m]); fma2(z1b, a1, w1[2*m+1]); }  \
        }                                                                   \
        if (DC0) UPDATE_CELL(z0a, z0b, c0, h0buf[wp_]);                     \
        /* Loop B: consumes H1 only -> z1 complete, z2ab partial */         \
        _Pragma("unroll")                                                   \
        for (int m = 0; m < 16; m++) {                                      \
            float4 q1 = H1_[m];                                             \
            u64 b0v = pk(q1.x, q1.y), b1v = pk(q1.z, q1.w);                 \
            if (DC1) { fma2(z1c, b0v, u1[2*m]); fma2(z1d, b1v, u1[2*m+1]); }\
            if (DC2) { fma2(z2a, b0v, w1[2*m]); fma2(z2b, b1v, w1[2*m+1]); }\
        }                                                                   \
        if (DC1) { z1a = addx2(z1a, z1c); z1b = addx2(z1b, z1d);            \
                   UPDATE_CELL(z1a, z1b, c1, h1buf[wp_]); }                 \
        /* Loop C: consumes H2 only -> z2 complete */                       \
        _Pragma("unroll")                                                   \
        for (int m = 0; m < 16; m++) {                                      \
            float4 q2 = H2_[m];                                             \
            if (DC2) { fma2(z2c, pk(q2.x, q2.y), u1[2*m]);                  \
                       fma2(z2d, pk(q2.z, q2.w), u1[2*m+1]); }              \
        }                                                                   \
        if (DC2) { z2a = addx2(z2a, z2c); z2b = addx2(z2b, z2d);            \
                   UPDATE_CELL(z2a, z2b, c2, h2buf[wp_]); }                 \
        __syncthreads();                                                    \
    }

    // Warm-up (peeled)
    TICK(0, 1, 0, 0)
    TICK(1, 1, 1, 0)
    // Branch-free main loop: tau = 2 .. SEQ-1  (2046 ticks)
#pragma unroll 2
    for (int tau = 2; tau < SEQ; tau++) {
        TICK(tau, 1, 1, 1)
    }
    // Drain (peeled)
    TICK(SEQ,     0, 1, 1)
    TICK(SEQ + 1, 0, 0, 1)

#undef TICK
#undef UPDATE_CELL

    // Final h2(SEQ-1) written at tick SEQ+1 to parity ((SEQ+1)&1)^1 = SEQ&1.
    const float* h2f = h2buf[SEQ & 1];

    // ---------------- Epilogue: y = relu(h2 @ Wf + bf) @ Wo + bo ------------
    if (j < 64) {
        float acc = bfv[j];
#pragma unroll
        for (int k = 0; k < 64; k++) acc = fmaf(h2f[k], Wf[k * 64 + j], acc);
        fs[j] = fmaxf(acc, 0.f);
    }
    __syncthreads();
    if (j < OUTD) {
        float acc = bo[j];
#pragma unroll
        for (int k = 0; k < 64; k++) acc = fmaf(fs[k], Wo[k * OUTD + j], acc);
        out[b * OUTD + j] = acc;
    }
}

// ===========================================================================
extern "C" void kernel_launch(void* const* d_in, const int* in_sizes, int n_in,
                              void* d_out, int out_size)
{
    const float* x  = (const float*)d_in[0];
    const float* W0 = (const float*)d_in[1];
    const float* U0 = (const float*)d_in[2];
    const float* b0 = (const float*)d_in[3];
    const float* W1 = (const float*)d_in[4];
    const float* U1 = (const float*)d_in[5];
    const float* b1 = (const float*)d_in[6];
    const float* Wf = (const float*)d_in[7];
    const float* bf = (const float*)d_in[8];
    const float* Wo = (const float*)d_in[9];
    const float* bo = (const float*)d_in[10];

    dim3 pg(BATCH, SEQ / 128);
    precompute_kernel<<<pg, 256>>>(x, W0, b0);
    rnn_kernel<<<BATCH, 256>>>(U0, W1, U1, b1, Wf, bf, Wo, bo, (float*)d_out);
}

// round 10
// speedup vs baseline: 1.2723x; 1.2723x over previous
#include <cuda_runtime.h>

#define BATCH 128
#define SEQ   2048
#define FEAT  64
#define UNITS 64
#define GATES 256   // 4*UNITS
#define OUTD  6

// Precomputed x@W0 + b0, PERMUTED column layout, [B][T][256] (+pad: pipeline prefetch overshoots)
__device__ float g_pre0[(size_t)BATCH * SEQ * GATES + 4 * GATES];

typedef unsigned long long u64;

// ---- packed f32x2 helpers -------------------------------------------------
__device__ __forceinline__ u64 pk(float lo, float hi) {
    u64 r; asm("mov.b64 %0, {%1, %2};" : "=l"(r) : "f"(lo), "f"(hi)); return r;
}
__device__ __forceinline__ void upk(u64 v, float& lo, float& hi) {
    asm("mov.b64 {%0, %1}, %2;" : "=f"(lo), "=f"(hi) : "l"(v));
}
__device__ __forceinline__ void fma2(u64& d, u64 a, u64 b) {
    asm("fma.rn.f32x2 %0, %1, %2, %0;" : "+l"(d) : "l"(a), "l"(b));
}
__device__ __forceinline__ u64 addx2(u64 a, u64 b) {
    u64 r; asm("add.rn.f32x2 %0, %1, %2;" : "=l"(r) : "l"(a), "l"(b)); return r;
}
__device__ __forceinline__ float red4(u64 a, u64 b) {
    float x0, x1, x2, x3; upk(a, x0, x1); upk(b, x2, x3);
    return (x0 + x1) + (x2 + x3);
}

// ---- hardware tanh (MUFU.TANH, sm_75+): 1 op, ~16 cyc ---------------------
__device__ __forceinline__ float tanh_ap(float x) {
    float r; asm("tanh.approx.f32 %0, %1;" : "=f"(r) : "f"(x)); return r;
}
// Unified gate activation:
//   tanh gate:    k=1,   off=0   ->  1*tanh(1*z)+0
//   sigmoid gate: k=0.5, off=0.5 ->  0.5*tanh(0.5*z)+0.5
__device__ __forceinline__ float gate_act(float z, float k, float off) {
    return fmaf(k, tanh_ap(k * z), off);
}

// Column permutation: column q <-> gate column (q&3)*64 + (q>>2)
__device__ __forceinline__ int PERM(int q) { return ((q & 3) << 6) + (q >> 2); }

// ===========================================================================
// Kernel 1: pre0[b][t][j] = (x[b][t] @ W0 + b0)[PERM(j)], 4-timestep unroll
// ===========================================================================
__global__ void __launch_bounds__(256) precompute_kernel(
    const float* __restrict__ x, const float* __restrict__ W0,
    const float* __restrict__ b0)
{
    __shared__ __align__(16) float xs[128 * FEAT];   // 32 KB
    const int b   = blockIdx.x;
    const int t0  = blockIdx.y * 128;
    const int j   = threadIdx.x;
    const int col = PERM(j);

    u64 w[32];
#pragma unroll
    for (int m = 0; m < 32; m++)
        w[m] = pk(W0[(2 * m) * GATES + col], W0[(2 * m + 1) * GATES + col]);
    const float bias = b0[col];

    const float4* xp = (const float4*)(x + ((size_t)b * SEQ + t0) * FEAT);
    float4* xsv = (float4*)xs;
    for (int i = j; i < 128 * FEAT / 4; i += 256) xsv[i] = xp[i];
    __syncthreads();

    float* outp = g_pre0 + ((size_t)b * SEQ + t0) * GATES;
    for (int t = 0; t < 128; t += 4) {
        u64 acc[8];
#pragma unroll
        for (int r = 0; r < 4; r++) { acc[2 * r] = pk(bias, 0.f); acc[2 * r + 1] = 0ull; }
        const float4* hx0 = (const float4*)(xs + (t + 0) * FEAT);
        const float4* hx1 = (const float4*)(xs + (t + 1) * FEAT);
        const float4* hx2 = (const float4*)(xs + (t + 2) * FEAT);
        const float4* hx3 = (const float4*)(xs + (t + 3) * FEAT);
#pragma unroll
        for (int m = 0; m < 16; m++) {
            float4 q0 = hx0[m];
            fma2(acc[0], pk(q0.x, q0.y), w[2 * m]);
            fma2(acc[1], pk(q0.z, q0.w), w[2 * m + 1]);
            float4 q1 = hx1[m];
            fma2(acc[2], pk(q1.x, q1.y), w[2 * m]);
            fma2(acc[3], pk(q1.z, q1.w), w[2 * m + 1]);
            float4 q2 = hx2[m];
            fma2(acc[4], pk(q2.x, q2.y), w[2 * m]);
            fma2(acc[5], pk(q2.z, q2.w), w[2 * m + 1]);
            float4 q3 = hx3[m];
            fma2(acc[6], pk(q3.x, q3.y), w[2 * m]);
            fma2(acc[7], pk(q3.z, q3.w), w[2 * m + 1]);
        }
#pragma unroll
        for (int r = 0; r < 4; r++)
            outp[(size_t)(t + r) * GATES + j] = red4(acc[2 * r], acc[2 * r + 1]);
    }
}

// ===========================================================================
// Kernel 2: persistent recurrence, CELLS PIPELINED ACROSS TIME (monolithic
// interleaved GEMV loop — R6 structure; staggered variants regress at this
// register pressure). 128 blocks x 256 threads; 1 barrier/tick; peeled ends.
// Tick tau: cell0 @ t=tau, cell1 @ t=tau-1, cell2 @ t=tau-2.
// ===========================================================================
__global__ void __launch_bounds__(256) rnn_kernel(
    const float* __restrict__ U0g, const float* __restrict__ W1g,
    const float* __restrict__ U1g, const float* __restrict__ b1g,
    const float* __restrict__ Wf,  const float* __restrict__ bfv,
    const float* __restrict__ Wo,  const float* __restrict__ bo,
    float* __restrict__ out)
{
    __shared__ __align__(16) float h0buf[2][UNITS];
    __shared__ __align__(16) float h1buf[2][UNITS];
    __shared__ __align__(16) float h2buf[2][UNITS];
    __shared__ __align__(16) float fs[64];

    const int j   = threadIdx.x;          // 0..255
    const int b   = blockIdx.x;
    const int col = PERM(j);
    const int u   = j >> 2;
    const bool wr  = ((j & 3) == 0);
    const bool isg = ((j & 3) == 2);
    const float ak  = isg ? 1.f : 0.5f;   // gate_act params (hoisted)
    const float aoff= isg ? 0.f : 0.5f;

    // Weight columns in registers, k-packed (96 u64 = 192 regs).
    u64 u0[32], w1[32], u1[32];
#pragma unroll
    for (int m = 0; m < 32; m++) {
        u0[m] = pk(U0g[(2 * m) * GATES + col], U0g[(2 * m + 1) * GATES + col]);
        w1[m] = pk(W1g[(2 * m) * GATES + col], W1g[(2 * m + 1) * GATES + col]);
        u1[m] = pk(U1g[(2 * m) * GATES + col], U1g[(2 * m + 1) * GATES + col]);
    }
    const float bias1 = b1g[col];

    float c0 = 0.f, c1 = 0.f, c2 = 0.f;   // valid on g==0 lanes
    if (j < UNITS) {
        h0buf[0][j] = 0.f; h0buf[1][j] = 0.f;
        h1buf[0][j] = 0.f; h1buf[1][j] = 0.f;
        h2buf[0][j] = 0.f; h2buf[1][j] = 0.f;
    }
    __syncthreads();

    const float* prep = g_pre0 + (size_t)b * SEQ * GATES + j;
    float pre = *prep;                    // pre for tau=0

#define UPDATE_CELL(ZA, ZB, CV, DST)                                        \
    {                                                                       \
        float z_ = red4(ZA, ZB);                                            \
        float a_  = gate_act(z_, ak, aoff);                                 \
        float v1_ = __shfl_xor_sync(0xffffffffu, a_, 1);                    \
        float v2_ = __shfl_xor_sync(0xffffffffu, a_, 2);                    \
        float v3_ = __shfl_xor_sync(0xffffffffu, a_, 3);                    \
        CV = v1_ * CV + a_ * v2_;                                           \
        float h_ = v3_ * tanh_ap(CV);                                       \
        if (wr) (DST)[u] = h_;                                              \
    }

#define TICK(TAU, DC0, DC1, DC2)                                            \
    {                                                                       \
        const int rp_ = (TAU) & 1, wp_ = rp_ ^ 1;                           \
        const float4* H0_ = (const float4*)h0buf[rp_];                      \
        const float4* H1_ = (const float4*)h1buf[rp_];                      \
        const float4* H2_ = (const float4*)h2buf[rp_];                      \
        u64 z0a = pk(pre, 0.f),   z0b = 0ull;                               \
        u64 z1a = pk(bias1, 0.f), z1b = 0ull, z1c = 0ull, z1d = 0ull;       \
        u64 z2a = pk(bias1, 0.f), z2b = 0ull, z2c = 0ull, z2d = 0ull;       \
        prep += GATES;                                                      \
        pre = *prep;                                                        \
        _Pragma("unroll")                                                   \
        for (int m = 0; m < 16; m++) {                                      \
            float4 q0 = H0_[m];                                             \
            u64 a0 = pk(q0.x, q0.y), a1 = pk(q0.z, q0.w);                   \
            if (DC0) { fma2(z0a, a0, u0[2*m]); fma2(z0b, a1, u0[2*m+1]); }  \
            if (DC1) { fma2(z1a, a0, w1[2*m]); fma2(z1b, a1, w1[2*m+1]); }  \
            float4 q1 = H1_[m];                                             \
            u64 b0v = pk(q1.x, q1.y), b1v = pk(q1.z, q1.w);                 \
            if (DC1) { fma2(z1c, b0v, u1[2*m]); fma2(z1d, b1v, u1[2*m+1]); }\
            if (DC2) { fma2(z2a, b0v, w1[2*m]); fma2(z2b, b1v, w1[2*m+1]); }\
            float4 q2 = H2_[m];                                             \
            if (DC2) { fma2(z2c, pk(q2.x, q2.y), u1[2*m]);                  \
                       fma2(z2d, pk(q2.z, q2.w), u1[2*m+1]); }              \
        }                                                                   \
        if (DC0) UPDATE_CELL(z0a, z0b, c0, h0buf[wp_]);                     \
        if (DC1) { z1a = addx2(z1a, z1c); z1b = addx2(z1b, z1d);            \
                   UPDATE_CELL(z1a, z1b, c1, h1buf[wp_]); }                 \
        if (DC2) { z2a = addx2(z2a, z2c); z2b = addx2(z2b, z2d);            \
                   UPDATE_CELL(z2a, z2b, c2, h2buf[wp_]); }                 \
        __syncthreads();                                                    \
    }

    // Warm-up (peeled)
    TICK(0, 1, 0, 0)
    TICK(1, 1, 1, 0)
    // Branch-free main loop: tau = 2 .. SEQ-1  (2046 ticks)
#pragma unroll 2
    for (int tau = 2; tau < SEQ; tau++) {
        TICK(tau, 1, 1, 1)
    }
    // Drain (peeled)
    TICK(SEQ,     0, 1, 1)
    TICK(SEQ + 1, 0, 0, 1)

#undef TICK
#undef UPDATE_CELL

    // Final h2(SEQ-1) written at tick SEQ+1 to parity ((SEQ+1)&1)^1 = SEQ&1.
    const float* h2f = h2buf[SEQ & 1];

    // ---------------- Epilogue: y = relu(h2 @ Wf + bf) @ Wo + bo ------------
    if (j < 64) {
        float acc = bfv[j];
#pragma unroll
        for (int k = 0; k < 64; k++) acc = fmaf(h2f[k], Wf[k * 64 + j], acc);
        fs[j] = fmaxf(acc, 0.f);
    }
    __syncthreads();
    if (j < OUTD) {
        float acc = bo[j];
#pragma unroll
        for (int k = 0; k < 64; k++) acc = fmaf(fs[k], Wo[k * OUTD + j], acc);
        out[b * OUTD + j] = acc;
    }
}

// ===========================================================================
extern "C" void kernel_launch(void* const* d_in, const int* in_sizes, int n_in,
                              void* d_out, int out_size)
{
    const float* x  = (const float*)d_in[0];
    const float* W0 = (const float*)d_in[1];
    const float* U0 = (const float*)d_in[2];
    const float* b0 = (const float*)d_in[3];
    const float* W1 = (const float*)d_in[4];
    const float* U1 = (const float*)d_in[5];
    const float* b1 = (const float*)d_in[6];
    const float* Wf = (const float*)d_in[7];
    const float* bf = (const float*)d_in[8];
    const float* Wo = (const float*)d_in[9];
    const float* bo = (const float*)d_in[10];

    dim3 pg(BATCH, SEQ / 128);
    precompute_kernel<<<pg, 256>>>(x, W0, b0);
    rnn_kernel<<<BATCH, 256>>>(U0, W1, U1, b1, Wf, bf, Wo, bo, (float*)d_out);
}